// round 2
// baseline (speedup 1.0000x reference)
#include <cuda_runtime.h>

#define T_STEPS 512
#define BATCH 256

// Ping-pong activation buffers, layout [t][feature(16 max)][batch]
__device__ __align__(16) float g_act[2][T_STEPS * 16 * BATCH];
// One flag per (layer, split, t). Consumers reset to 0 after consuming,
// so the array is back to all-zero at the end of every run (graph-replay safe).
__device__ unsigned g_flags[64 * 4 * T_STEPS];

// ---------------------------------------------------------------------------
// Primitives
// ---------------------------------------------------------------------------
__device__ __forceinline__ unsigned ld_acq(const unsigned* p) {
    unsigned v;
    asm volatile("ld.acquire.gpu.global.u32 %0, [%1];" : "=r"(v) : "l"(p) : "memory");
    return v;
}
__device__ __forceinline__ void st_rel(unsigned* p, unsigned v) {
    asm volatile("st.release.gpu.global.u32 [%0], %1;" :: "l"(p), "r"(v) : "memory");
}
__device__ __forceinline__ void st_rlx(unsigned* p, unsigned v) {
    asm volatile("st.relaxed.gpu.global.u32 [%0], %1;" :: "l"(p), "r"(v) : "memory");
}

// Packed 2-wide fp32 FMA (Blackwell f32x2 path): 2 MACs per instruction.
__device__ __forceinline__ float2 ffma2(float2 a, float2 b, float2 c) {
    float2 d;
    asm("fma.rn.f32x2 %0, %1, %2, %3;"
        : "=l"(reinterpret_cast<unsigned long long&>(d))
        : "l"(reinterpret_cast<unsigned long long&>(a)),
          "l"(reinterpret_cast<unsigned long long&>(b)),
          "l"(reinterpret_cast<unsigned long long&>(c)));
    return d;
}

// Accurate fast activations (EX2 + RCP, rel err ~1e-6; safe over 160 layers)
__device__ __forceinline__ float fsig(float x) {
    float e = __expf(-x);
    return __fdividef(1.f, 1.f + e);
}
__device__ __forceinline__ float ftanhf(float x) {
    float e = __expf(-2.f * x);
    return __fdividef(1.f - e, 1.f + e);
}

// ---------------------------------------------------------------------------
// Per-layer wavefront loop. One block = (layer l, batch split s).
// Thread mapping: j = tid / GROUPS (hidden unit), group = tid % GROUPS,
// each thread handles NB batch-pairs (float2 over 2 adjacent batch elems).
// ---------------------------------------------------------------------------
template<int H, int DIN, int NS, int BLOCK, bool FIRST, bool RELU>
__device__ __forceinline__ void layer_loop(
    const float2* __restrict__ sW, const float2* __restrict__ sB,
    float2* xs, float2* hs,
    const float* __restrict__ bufin, float* __restrict__ bufout,
    unsigned* fin, unsigned* fout, bool last, int b0)
{
    constexpr int KMAX   = 2 * H;
    constexpr int Bs     = BATCH / NS;
    constexpr int BPC    = Bs / 2;          // batch-pairs per block
    constexpr int GROUPS = BLOCK / H;
    constexpr int NB     = BPC / GROUPS;    // batch-pairs per thread

    const int tid   = threadIdx.x;
    const int j     = tid / GROUPS;
    const int group = tid % GROUPS;

    float2 c[NB];
#pragma unroll
    for (int n = 0; n < NB; n++) c[n] = make_float2(0.f, 0.f);

    for (int t = 0; t < T_STEPS; t++) {
        if (!FIRST) {
            if (tid == 0) {
                while (ld_acq(fin + t) == 0) { }
                st_rlx(fin + t, 0u);   // reset for next graph replay
            }
        }
        __syncthreads();

        // Stage this timestep's input slice into smem
#pragma unroll
        for (int i = tid; i < DIN * BPC; i += BLOCK) {
            int m = i / BPC, bp = i % BPC;
            float2 v = *reinterpret_cast<const float2*>(
                &bufin[(t * 16 + m) * BATCH + b0 + 2 * bp]);
            if (RELU) { v.x = fmaxf(v.x, 0.f); v.y = fmaxf(v.y, 0.f); }
            xs[i] = v;
        }
        __syncthreads();

        const float2* hsR = hs + (t & 1) * (H * BPC);
        float2*       hsW = hs + ((t & 1) ^ 1) * (H * BPC);

        float2 acc[4][NB];
#pragma unroll
        for (int q = 0; q < 4; q++) {
            float2 b = sB[q * H + j];
#pragma unroll
            for (int n = 0; n < NB; n++) acc[q][n] = b;
        }

        // Input contribution
#pragma unroll
        for (int k = 0; k < DIN; k++) {
            float2 w[4];
#pragma unroll
            for (int q = 0; q < 4; q++) w[q] = sW[(q * H + j) * KMAX + k];
#pragma unroll
            for (int n = 0; n < NB; n++) {
                float2 v = xs[k * BPC + n * GROUPS + group];
#pragma unroll
                for (int q = 0; q < 4; q++) acc[q][n] = ffma2(w[q], v, acc[q][n]);
            }
        }
        // Recurrent contribution
#pragma unroll
        for (int k = 0; k < H; k++) {
            float2 w[4];
#pragma unroll
            for (int q = 0; q < 4; q++) w[q] = sW[(q * H + j) * KMAX + DIN + k];
#pragma unroll
            for (int n = 0; n < NB; n++) {
                float2 v = hsR[k * BPC + n * GROUPS + group];
#pragma unroll
                for (int q = 0; q < 4; q++) acc[q][n] = ffma2(w[q], v, acc[q][n]);
            }
        }

        // Gate activations + state update (c stays in registers)
#pragma unroll
        for (int n = 0; n < NB; n++) {
            float ix = fsig(acc[0][n].x),  iy = fsig(acc[0][n].y);
            float fx = fsig(acc[1][n].x),  fy = fsig(acc[1][n].y);
            float gx = ftanhf(acc[2][n].x), gy = ftanhf(acc[2][n].y);
            float ox = fsig(acc[3][n].x),  oy = fsig(acc[3][n].y);
            float cx = fx * c[n].x + ix * gx;
            float cy = fy * c[n].y + iy * gy;
            c[n] = make_float2(cx, cy);
            float2 h2 = make_float2(ox * ftanhf(cx), oy * ftanhf(cy));
            int bp = n * GROUPS + group;
            hsW[j * BPC + bp] = h2;
            *reinterpret_cast<float2*>(
                &bufout[(t * 16 + j) * BATCH + b0 + 2 * bp]) = h2;
        }
        __syncthreads();
        if (!last && tid == 0) st_rel(fout + t, 1u);
    }
}

// ---------------------------------------------------------------------------
// Stack kernel: grid = L * NS blocks; block (l, s). Lower layers = lower bid.
// ---------------------------------------------------------------------------
template<int H, int DIN0, int L, int NS, int BLOCK, bool RELU_IN>
__global__ void __launch_bounds__(BLOCK)
lstm_stack_kernel(const float* __restrict__ Wih0, const float* __restrict__ Whh0,
                  const float* __restrict__ bih0, const float* __restrict__ bhh0,
                  const float* __restrict__ Wih,  const float* __restrict__ Whh,
                  const float* __restrict__ bih,  const float* __restrict__ bhh)
{
    constexpr int G = 4 * H, KMAX = 2 * H, Bs = BATCH / NS, BPC = Bs / 2;

    __shared__ float2 sW[G * KMAX];   // weights, duplicated into both f32x2 halves
    __shared__ float2 sB[G];
    __shared__ float2 xs[H * BPC];
    __shared__ float2 hs[2 * H * BPC]; // double-buffered h state

    const int l = blockIdx.x / NS;
    const int s = blockIdx.x % NS;
    const int tid = threadIdx.x;

    const float* wih = l ? (Wih + (size_t)(l - 1) * G * H) : Wih0;
    const float* whh = l ? (Whh + (size_t)(l - 1) * G * H) : Whh0;
    const float* bi  = l ? (bih + (l - 1) * G) : bih0;
    const float* bh  = l ? (bhh + (l - 1) * G) : bhh0;
    const int DIN = l ? H : DIN0;

    for (int i = tid; i < G * KMAX; i += BLOCK) {
        int g = i / KMAX, k = i % KMAX;
        float w = 0.f;
        if (k < DIN)          w = wih[g * DIN + k];
        else if (k < DIN + H) w = whh[g * H + (k - DIN)];
        sW[i] = make_float2(w, w);
    }
    for (int i = tid; i < G; i += BLOCK) {
        float b = bi[i] + bh[i];
        sB[i] = make_float2(b, b);
    }
    for (int i = tid; i < H * BPC; i += BLOCK) hs[i] = make_float2(0.f, 0.f);
    // (ordering covered by the first __syncthreads inside layer_loop)

    const float* bufin  = g_act[l & 1];
    float*       bufout = g_act[(l + 1) & 1];
    unsigned* fin  = g_flags + (size_t)((l > 0 ? (l - 1) : 0) * NS + s) * T_STEPS;
    unsigned* fout = g_flags + (size_t)(l * NS + s) * T_STEPS;
    const bool last = (l == L - 1);
    const int  b0 = s * Bs;

    if (l == 0)
        layer_loop<H, DIN0, NS, BLOCK, true, RELU_IN>(sW, sB, xs, hs, bufin, bufout, fin, fout, last, b0);
    else
        layer_loop<H, H, NS, BLOCK, false, false>(sW, sB, xs, hs, bufin, bufout, fin, fout, last, b0);
}

// ---------------------------------------------------------------------------
// Pre: transpose x (T,B,2) -> g_act[0][t][m][b].  Post: ReLU + FC(16->4).
// ---------------------------------------------------------------------------
__global__ void pre_kernel(const float* __restrict__ x) {
    int t = blockIdx.x, b = threadIdx.x;
    float2 v = *reinterpret_cast<const float2*>(&x[((size_t)t * BATCH + b) * 2]);
    g_act[0][(t * 16 + 0) * BATCH + b] = v.x;
    g_act[0][(t * 16 + 1) * BATCH + b] = v.y;
}

__global__ void fc_kernel(const float* __restrict__ fcW, const float* __restrict__ fcb,
                          float* __restrict__ out) {
    int t = blockIdx.x, b = threadIdx.x;
    float v[16];
#pragma unroll
    for (int m = 0; m < 16; m++)
        v[m] = fmaxf(g_act[0][(t * 16 + m) * BATCH + b], 0.f);
#pragma unroll
    for (int q = 0; q < 4; q++) {
        float a = fcb[q];
#pragma unroll
        for (int m = 0; m < 16; m++) a = fmaf(v[m], fcW[q * 16 + m], a);
        out[((size_t)t * BATCH + b) * 4 + q] = a;
    }
}

// ---------------------------------------------------------------------------
// Launch. Inputs (metadata order):
// 0:x, 1-8:l1(Wih0,Whh0,bih0,bhh0,Wih,Whh,bih,bhh), 9-16:l2, 17-24:l3,
// 25:fc_W, 26:fc_b
// ---------------------------------------------------------------------------
extern "C" void kernel_launch(void* const* d_in, const int* in_sizes, int n_in,
                              void* d_out, int out_size) {
    const float* x = (const float*)d_in[0];
#define F(i) ((const float*)d_in[i])

    pre_kernel<<<T_STEPS, BATCH>>>(x);

    // Stack 1: H=4,  Din0=2, L=32, 4 batch-splits, 128-thread blocks
    lstm_stack_kernel<4, 2, 32, 4, 128, false><<<32 * 4, 128>>>(
        F(1), F(2), F(3), F(4), F(5), F(6), F(7), F(8));

    // Stack 2: H=8,  Din0=4, L=64, 2 batch-splits, 256-thread blocks (ReLU on input)
    lstm_stack_kernel<8, 4, 64, 2, 256, true><<<64 * 2, 256>>>(
        F(9), F(10), F(11), F(12), F(13), F(14), F(15), F(16));

    // Stack 3: H=16, Din0=8, L=64, 2 batch-splits, 256-thread blocks (ReLU on input)
    lstm_stack_kernel<16, 8, 64, 2, 256, true><<<64 * 2, 256>>>(
        F(17), F(18), F(19), F(20), F(21), F(22), F(23), F(24));

    // ReLU + FC
    fc_kernel<<<T_STEPS, BATCH>>>(F(25), F(26), (float*)d_out);
#undef F
}

// round 3
// speedup vs baseline: 1.2056x; 1.2056x over previous
#include <cuda_runtime.h>

#define T_STEPS 512
#define BATCH   256
#define BPC     128          // batch pairs (float2 over adjacent batch elems)
#define NSTAGE  144          // 16 (stack1, 2 layers each) + 64 (stack2) + 64 (stack3)
#define BLOCK   256

// Ping-pong activation buffers, layout [t][feature(16)][batch]
__device__ __align__(16) float g_act[2][T_STEPS * 16 * BATCH];
// One flag per (stage, t); consumer resets to 0 => replay-safe.
__device__ unsigned g_flags[NSTAGE * T_STEPS];

// ---------------------------------------------------------------------------
// Primitives
// ---------------------------------------------------------------------------
__device__ __forceinline__ unsigned ld_acq(const unsigned* p) {
    unsigned v;
    asm volatile("ld.acquire.gpu.global.u32 %0, [%1];" : "=r"(v) : "l"(p) : "memory");
    return v;
}
__device__ __forceinline__ void st_rel(unsigned* p, unsigned v) {
    asm volatile("st.release.gpu.global.u32 [%0], %1;" :: "l"(p), "r"(v) : "memory");
}
__device__ __forceinline__ void st_rlx(unsigned* p, unsigned v) {
    asm volatile("st.relaxed.gpu.global.u32 [%0], %1;" :: "l"(p), "r"(v) : "memory");
}
__device__ __forceinline__ float2 ffma2(float2 a, float2 b, float2 c) {
    float2 d;
    asm("fma.rn.f32x2 %0, %1, %2, %3;"
        : "=l"(reinterpret_cast<unsigned long long&>(d))
        : "l"(reinterpret_cast<unsigned long long&>(a)),
          "l"(reinterpret_cast<unsigned long long&>(b)),
          "l"(reinterpret_cast<unsigned long long&>(c)));
    return d;
}
__device__ __forceinline__ float fsig(float x) {
    float e = __expf(-x);
    return __fdividef(1.f, 1.f + e);
}
__device__ __forceinline__ float ftanhf(float x) {
    float e = __expf(-2.f * x);
    return __fdividef(1.f - e, 1.f + e);
}

// ---------------------------------------------------------------------------
// One LSTM cell step for one block (full batch).
// Thread mapping: j = tid / GROUPS (hidden unit), group = tid % GROUPS,
// batch-pair bp = n*GROUPS + group  (contiguous across warp lanes).
// xh: rows [0,DIN) input, rows [DIN,DIN+H) h(t-1).  hout may alias xh+DIN*BPC.
// ---------------------------------------------------------------------------
template<int H, int DIN>
__device__ __forceinline__ void lstm_cell(
    const float2* __restrict__ sW,     // [4H][DIN+H] duplicated f32x2
    const float2 bias[4],
    const float2* __restrict__ xh,
    float2* __restrict__ hout,
    float* __restrict__ gout,          // bufout + t*16*BATCH, or nullptr
    float2* __restrict__ c,
    int j, int group)
{
    constexpr int GROUPS = BLOCK / H;
    constexpr int NB = BPC / GROUPS;
    constexpr int KM = DIN + H;

    float2 acc[4][NB];
#pragma unroll
    for (int q = 0; q < 4; q++)
#pragma unroll
        for (int n = 0; n < NB; n++) acc[q][n] = bias[q];

#pragma unroll
    for (int k = 0; k < KM; k++) {
        float2 w0 = sW[(0 * H + j) * KM + k];
        float2 w1 = sW[(1 * H + j) * KM + k];
        float2 w2 = sW[(2 * H + j) * KM + k];
        float2 w3 = sW[(3 * H + j) * KM + k];
#pragma unroll
        for (int n = 0; n < NB; n++) {
            float2 v = xh[k * BPC + n * GROUPS + group];
            acc[0][n] = ffma2(w0, v, acc[0][n]);
            acc[1][n] = ffma2(w1, v, acc[1][n]);
            acc[2][n] = ffma2(w2, v, acc[2][n]);
            acc[3][n] = ffma2(w3, v, acc[3][n]);
        }
    }
    __syncthreads();   // all xh reads done before hout writes (hout aliases xh)

#pragma unroll
    for (int n = 0; n < NB; n++) {
        float ix = fsig(acc[0][n].x),   iy = fsig(acc[0][n].y);
        float fx = fsig(acc[1][n].x),   fy = fsig(acc[1][n].y);
        float gx = ftanhf(acc[2][n].x), gy = ftanhf(acc[2][n].y);
        float ox = fsig(acc[3][n].x),   oy = fsig(acc[3][n].y);
        float cx = fmaf(fx, c[n].x, ix * gx);
        float cy = fmaf(fy, c[n].y, iy * gy);
        c[n] = make_float2(cx, cy);
        float2 h2 = make_float2(ox * ftanhf(cx), oy * ftanhf(cy));
        int bp = n * GROUPS + group;
        hout[j * BPC + bp] = h2;
        if (gout)
            *reinterpret_cast<float2*>(&gout[j * BATCH + 2 * bp]) = h2;
    }
}

template<int H, int DIN>
__device__ __forceinline__ void load_w(float2* sW, const float* __restrict__ wih,
                                       const float* __restrict__ whh, int tid)
{
    constexpr int G = 4 * H, KM = DIN + H;
    for (int i = tid; i < G * KM; i += BLOCK) {
        int g = i / KM, k = i % KM;
        float w = (k < DIN) ? wih[g * DIN + k] : whh[g * H + (k - DIN)];
        sW[i] = make_float2(w, w);
    }
}

template<int H>
__device__ __forceinline__ void load_bias(float2 bias[4], const float* bi,
                                          const float* bh, int j)
{
#pragma unroll
    for (int q = 0; q < 4; q++) {
        float b = bi[q * H + j] + bh[q * H + j];
        bias[q] = make_float2(b, b);
    }
}

template<int DIN, bool RELU>
__device__ __forceinline__ void stage_x(float2* xrows, const float* __restrict__ bin,
                                        int tid)
{
    for (int i = tid; i < DIN * (BPC / 2); i += BLOCK) {
        int m = i / (BPC / 2), q4 = i % (BPC / 2);
        float4 v = *reinterpret_cast<const float4*>(&bin[m * BATCH + 4 * q4]);
        if (RELU) {
            v.x = fmaxf(v.x, 0.f); v.y = fmaxf(v.y, 0.f);
            v.z = fmaxf(v.z, 0.f); v.w = fmaxf(v.w, 0.f);
        }
        *reinterpret_cast<float4*>(&xrows[m * BPC + 2 * q4]) = v;
    }
}

// ---------------------------------------------------------------------------
// Stage with one layer (stacks 2 and 3). Always polls its input flag.
// ---------------------------------------------------------------------------
template<int H, int DIN, bool RELU>
__device__ void run_stage_single(
    const float* wih, const float* whh, const float* bi, const float* bh,
    float2* spool, const float* bufin, float* bufout,
    unsigned* fin, unsigned* fout)
{
    constexpr int G = 4 * H, KM = DIN + H;
    constexpr int GROUPS = BLOCK / H, NB = BPC / GROUPS;
    float2* sW = spool;
    float2* xh = spool + G * KM;

    const int tid = threadIdx.x;
    const int j = tid / GROUPS, group = tid % GROUPS;

    load_w<H, DIN>(sW, wih, whh, tid);
    float2 bias[4];
    load_bias<H>(bias, bi, bh, j);
    for (int i = tid; i < H * BPC; i += BLOCK) xh[DIN * BPC + i] = make_float2(0.f, 0.f);
    float2 c[NB];
#pragma unroll
    for (int n = 0; n < NB; n++) c[n] = make_float2(0.f, 0.f);

    for (int t = 0; t < T_STEPS; t++) {
        if (tid == 0) {
            while (ld_acq(fin + t) == 0) { }
            st_rlx(fin + t, 0u);
        }
        __syncthreads();
        stage_x<DIN, RELU>(xh, bufin + (size_t)t * 16 * BATCH, tid);
        __syncthreads();
        lstm_cell<H, DIN>(sW, bias, xh, xh + DIN * BPC,
                          bufout + (size_t)t * 16 * BATCH, c, j, group);
        __syncthreads();
        if (fout && tid == 0) st_rel(fout + t, 1u);
    }
}

// ---------------------------------------------------------------------------
// Stack-1 stage: two packed H=4 layers, inner handoff through smem.
// ---------------------------------------------------------------------------
template<int DINA, bool FIRST>
__device__ void run_stage_s1(
    const float* wihA, const float* whhA, const float* biA, const float* bhA,
    const float* wihB, const float* whhB, const float* biB, const float* bhB,
    float2* spool, const float* bufin, float* bufout,
    unsigned* fin, unsigned* fout)
{
    constexpr int H = 4, G = 16, KMA = DINA + H, KMB = 2 * H;
    constexpr int GROUPS = BLOCK / H, NB = BPC / GROUPS;   // 64, 2
    float2* sWA = spool;
    float2* sWB = sWA + G * KMA;
    float2* xh  = sWB + G * KMB;    // rows: xA(DINA) | hA(4) | hB(4)

    const int tid = threadIdx.x;
    const int j = tid / GROUPS, group = tid % GROUPS;

    load_w<H, DINA>(sWA, wihA, whhA, tid);
    load_w<H, H>(sWB, wihB, whhB, tid);
    float2 biasA[4], biasB[4];
    load_bias<H>(biasA, biA, bhA, j);
    load_bias<H>(biasB, biB, bhB, j);
    for (int i = tid; i < 2 * H * BPC; i += BLOCK)
        xh[DINA * BPC + i] = make_float2(0.f, 0.f);
    float2 cA[NB], cB[NB];
#pragma unroll
    for (int n = 0; n < NB; n++) { cA[n] = make_float2(0.f, 0.f); cB[n] = make_float2(0.f, 0.f); }

    for (int t = 0; t < T_STEPS; t++) {
        if (!FIRST && tid == 0) {
            while (ld_acq(fin + t) == 0) { }
            st_rlx(fin + t, 0u);
        }
        __syncthreads();
        stage_x<DINA, false>(xh, bufin + (size_t)t * 16 * BATCH, tid);
        __syncthreads();
        lstm_cell<H, DINA>(sWA, biasA, xh, xh + DINA * BPC, nullptr, cA, j, group);
        __syncthreads();
        lstm_cell<H, H>(sWB, biasB, xh + DINA * BPC, xh + (DINA + H) * BPC,
                        bufout + (size_t)t * 16 * BATCH, cB, j, group);
        __syncthreads();
        if (tid == 0) st_rel(fout + t, 1u);
    }
}

// ---------------------------------------------------------------------------
// Fused pipeline kernel: 144 co-resident stages (<= 148 SMs => deadlock-free)
// ---------------------------------------------------------------------------
__global__ void __launch_bounds__(BLOCK, 1)
lstm_pipe(const float* l1_Wih0, const float* l1_Whh0, const float* l1_bih0, const float* l1_bhh0,
          const float* l1_Wih,  const float* l1_Whh,  const float* l1_bih,  const float* l1_bhh,
          const float* l2_Wih0, const float* l2_Whh0, const float* l2_bih0, const float* l2_bhh0,
          const float* l2_Wih,  const float* l2_Whh,  const float* l2_bih,  const float* l2_bhh,
          const float* l3_Wih0, const float* l3_Whh0, const float* l3_bih0, const float* l3_bhh0,
          const float* l3_Wih,  const float* l3_Whh,  const float* l3_bih,  const float* l3_bhh)
{
    __shared__ __align__(16) float2 spool[6144];   // 48KB
    const int s = blockIdx.x;
    const float* bufin  = g_act[s & 1];
    float*       bufout = g_act[(s + 1) & 1];
    unsigned* fin  = g_flags + (size_t)(s > 0 ? s - 1 : 0) * T_STEPS;
    unsigned* fout = (s == NSTAGE - 1) ? nullptr
                                       : g_flags + (size_t)s * T_STEPS;

    if (s < 16) {
        const int lA = 2 * s, lB = 2 * s + 1;
        const float* wihA = lA ? l1_Wih + (size_t)(lA - 1) * 16 * 4 : l1_Wih0;
        const float* whhA = lA ? l1_Whh + (size_t)(lA - 1) * 16 * 4 : l1_Whh0;
        const float* biA  = lA ? l1_bih + (lA - 1) * 16 : l1_bih0;
        const float* bhA  = lA ? l1_bhh + (lA - 1) * 16 : l1_bhh0;
        const float* wihB = l1_Wih + (size_t)(lB - 1) * 16 * 4;
        const float* whhB = l1_Whh + (size_t)(lB - 1) * 16 * 4;
        const float* biB  = l1_bih + (lB - 1) * 16;
        const float* bhB  = l1_bhh + (lB - 1) * 16;
        if (s == 0)
            run_stage_s1<2, true>(wihA, whhA, biA, bhA, wihB, whhB, biB, bhB,
                                  spool, bufin, bufout, fin, fout);
        else
            run_stage_s1<4, false>(wihA, whhA, biA, bhA, wihB, whhB, biB, bhB,
                                   spool, bufin, bufout, fin, fout);
    } else if (s < 80) {
        const int l = s - 16;
        const float* wih = l ? l2_Wih + (size_t)(l - 1) * 32 * 8 : l2_Wih0;
        const float* whh = l ? l2_Whh + (size_t)(l - 1) * 32 * 8 : l2_Whh0;
        const float* bi  = l ? l2_bih + (l - 1) * 32 : l2_bih0;
        const float* bh  = l ? l2_bhh + (l - 1) * 32 : l2_bhh0;
        if (l == 0)
            run_stage_single<8, 4, true>(wih, whh, bi, bh, spool, bufin, bufout, fin, fout);
        else
            run_stage_single<8, 8, false>(wih, whh, bi, bh, spool, bufin, bufout, fin, fout);
    } else {
        const int l = s - 80;
        const float* wih = l ? l3_Wih + (size_t)(l - 1) * 64 * 16 : l3_Wih0;
        const float* whh = l ? l3_Whh + (size_t)(l - 1) * 64 * 16 : l3_Whh0;
        const float* bi  = l ? l3_bih + (l - 1) * 64 : l3_bih0;
        const float* bh  = l ? l3_bhh + (l - 1) * 64 : l3_bhh0;
        if (l == 0)
            run_stage_single<16, 8, true>(wih, whh, bi, bh, spool, bufin, bufout, fin, fout);
        else
            run_stage_single<16, 16, false>(wih, whh, bi, bh, spool, bufin, bufout, fin, fout);
    }
}

// ---------------------------------------------------------------------------
// Pre: transpose x (T,B,2) -> g_act[0][t][m][b].  Post: ReLU + FC(16->4).
// ---------------------------------------------------------------------------
__global__ void pre_kernel(const float* __restrict__ x) {
    int t = blockIdx.x, b = threadIdx.x;
    float2 v = *reinterpret_cast<const float2*>(&x[((size_t)t * BATCH + b) * 2]);
    g_act[0][(t * 16 + 0) * BATCH + b] = v.x;
    g_act[0][(t * 16 + 1) * BATCH + b] = v.y;
}

__global__ void fc_kernel(const float* __restrict__ fcW, const float* __restrict__ fcb,
                          float* __restrict__ out) {
    int t = blockIdx.x, b = threadIdx.x;
    float v[16];
#pragma unroll
    for (int m = 0; m < 16; m++)
        v[m] = fmaxf(g_act[0][(t * 16 + m) * BATCH + b], 0.f);
#pragma unroll
    for (int q = 0; q < 4; q++) {
        float a = fcb[q];
#pragma unroll
        for (int m = 0; m < 16; m++) a = fmaf(v[m], fcW[q * 16 + m], a);
        out[((size_t)t * BATCH + b) * 4 + q] = a;
    }
}

// ---------------------------------------------------------------------------
extern "C" void kernel_launch(void* const* d_in, const int* in_sizes, int n_in,
                              void* d_out, int out_size) {
#define F(i) ((const float*)d_in[i])
    pre_kernel<<<T_STEPS, BATCH>>>(F(0));
    lstm_pipe<<<NSTAGE, BLOCK>>>(
        F(1), F(2), F(3), F(4), F(5), F(6), F(7), F(8),
        F(9), F(10), F(11), F(12), F(13), F(14), F(15), F(16),
        F(17), F(18), F(19), F(20), F(21), F(22), F(23), F(24));
    fc_kernel<<<T_STEPS, BATCH>>>(F(25), F(26), (float*)d_out);
#undef F
}

// round 4
// speedup vs baseline: 1.3022x; 1.0801x over previous
#include <cuda_runtime.h>

#define T_STEPS 512
#define BATCH   256
#define BLOCK   256
#define NFLAGS  168     // 8 stack1 + 32 stack2 + 128 stack3 stage flags
#define GRID    168

// Ping-pong activation buffers, layout [t][feature(16)][batch]
__device__ __align__(16) float g_act[2][T_STEPS * 16 * BATCH];
// One flag per (stage, t). Never reset by consumers (multi-consumer);
// cleared by pre_kernel at the start of every replay.
__device__ unsigned g_flags[NFLAGS * T_STEPS];

// ---------------------------------------------------------------------------
__device__ __forceinline__ unsigned ld_acq(const unsigned* p) {
    unsigned v;
    asm volatile("ld.acquire.gpu.global.u32 %0, [%1];" : "=r"(v) : "l"(p) : "memory");
    return v;
}
__device__ __forceinline__ void st_rel(unsigned* p, unsigned v) {
    asm volatile("st.release.gpu.global.u32 [%0], %1;" :: "l"(p), "r"(v) : "memory");
}
__device__ __forceinline__ float2 ffma2(float2 a, float2 b, float2 c) {
    float2 d;
    asm("fma.rn.f32x2 %0, %1, %2, %3;"
        : "=l"(reinterpret_cast<unsigned long long&>(d))
        : "l"(reinterpret_cast<unsigned long long&>(a)),
          "l"(reinterpret_cast<unsigned long long&>(b)),
          "l"(reinterpret_cast<unsigned long long&>(c)));
    return d;
}

// LSTM cell nonlinearity, shared-denominator form: 5 ex2 + 2 rcp = 7 MUFU.
// Exactly sig(f)*c + sig(i)*tanh(g); h = sig(o)*tanh(c'). Clamp +-15 (err<4e-7).
__device__ __forceinline__ float cell_one(float gi, float gf, float gg, float go,
                                          float& c) {
    gi = fminf(fmaxf(gi, -15.f), 15.f);
    gf = fminf(fmaxf(gf, -15.f), 15.f);
    gg = fminf(fmaxf(gg, -15.f), 15.f);
    go = fminf(fmaxf(go, -15.f), 15.f);
    float a  = __expf(-gi);
    float fe = __expf(-gf);
    float b  = __expf(-2.f * gg);
    float na = 1.f + a, nf = 1.f + fe, nb = 1.f + b;
    float num = fmaf(c * na, nb, (1.f - b) * nf);
    c = __fdividef(num, nf * na * nb);
    float ct = fminf(fmaxf(c, -15.f), 15.f);
    float d  = __expf(-2.f * ct);
    float oe = __expf(-go);
    return __fdividef(1.f - d, (1.f + oe) * (1.f + d));
}

// ---------------------------------------------------------------------------
// Weight fill: layer into sW (4H x 2H, f32x2-duplicated, k<DIN from Wih,
// k in [DIN,H) zero-padded, k in [H,2H) from Whh) and bias into sB.
// ---------------------------------------------------------------------------
template<int H, int DIN0>
__device__ void fill_layer(float2* W, float* B,
                           const float* Wih0, const float* Whh0,
                           const float* bih0, const float* bhh0,
                           const float* Wih,  const float* Whh,
                           const float* bih,  const float* bhh, int l) {
    constexpr int G = 4 * H, KM = 2 * H;
    const float* wi = l ? Wih + (size_t)(l - 1) * G * H : Wih0;
    const float* wh = l ? Whh + (size_t)(l - 1) * G * H : Whh0;
    const float* bi = l ? bih + (l - 1) * G : bih0;
    const float* bh = l ? bhh + (l - 1) * G : bhh0;
    const int din = l ? H : DIN0;
    const int tid = threadIdx.x;
    for (int i = tid; i < G * KM; i += BLOCK) {
        int g = i / KM, k = i % KM;
        float w = 0.f;
        if (k < din)     w = wi[g * din + k];
        else if (k >= H) w = wh[g * H + (k - H)];
        W[i] = make_float2(w, w);
    }
    for (int i = tid; i < G; i += BLOCK) B[i] = bi[i] + bh[i];
}

// ---------------------------------------------------------------------------
// Steady-state loop for one pipeline stage (PACK layers fused in smem).
// rows layout: [0,H) staged input (upper rows zero-padded for first layers),
// then h rows of packed layer p at [(p+1)H, (p+2)H).
// ---------------------------------------------------------------------------
template<int H, int PACK, int BPC_, int DSTAGE, bool FIRST, bool RELU, bool LAST>
__device__ void stage_loop(const float2* __restrict__ sW, const float* __restrict__ sB,
                           float2* rows,
                           const float* __restrict__ bufin, float* __restrict__ bufout,
                           const unsigned* fin, unsigned* fout, int b0) {
    constexpr int GROUPS = BLOCK / H;
    constexpr int NB = BPC_ / GROUPS;
    constexpr int KM = 2 * H;
    const int tid = threadIdx.x;
    const int j = tid / GROUPS, group = tid % GROUPS;

    float2 c[PACK][NB];
#pragma unroll
    for (int p = 0; p < PACK; p++)
#pragma unroll
        for (int n = 0; n < NB; n++) c[p][n] = make_float2(0.f, 0.f);

    for (int i = tid; i < H * (PACK + 1) * BPC_; i += BLOCK)
        rows[i] = make_float2(0.f, 0.f);
    __syncthreads();   // also covers weight/bias fill

    for (int t = 0; t < T_STEPS; t++) {
        if (!FIRST) {
            const unsigned* f = fin + t;
            while (ld_acq(f) == 0) { }
        }
        // Stage this timestep's input slice (L2-fresh loads).
        const float* bin = bufin + (size_t)t * 16 * BATCH + b0;
#pragma unroll
        for (int i = tid; i < DSTAGE * (BPC_ / 2); i += BLOCK) {
            int m = i / (BPC_ / 2), q4 = i % (BPC_ / 2);
            float4 v = __ldcg(reinterpret_cast<const float4*>(&bin[m * BATCH + 4 * q4]));
            if (RELU) {
                v.x = fmaxf(v.x, 0.f); v.y = fmaxf(v.y, 0.f);
                v.z = fmaxf(v.z, 0.f); v.w = fmaxf(v.w, 0.f);
            }
            *reinterpret_cast<float4*>(&rows[m * BPC_ + 2 * q4]) = v;
        }
        __syncthreads();

        float* bout = bufout + (size_t)t * 16 * BATCH + b0;
#pragma unroll
        for (int p = 0; p < PACK; p++) {
            const float2* W   = sW + p * 4 * H * KM;
            const float*  B   = sB + p * 4 * H;
            const float2* vin = rows + p * H * BPC_;

            float2 acc[4][NB];
#pragma unroll
            for (int q = 0; q < 4; q++) {
                float bv = B[q * H + j];
#pragma unroll
                for (int n = 0; n < NB; n++) acc[q][n] = make_float2(bv, bv);
            }
#pragma unroll
            for (int k = 0; k < KM; k++) {
                float2 w0 = W[(0 * H + j) * KM + k];
                float2 w1 = W[(1 * H + j) * KM + k];
                float2 w2 = W[(2 * H + j) * KM + k];
                float2 w3 = W[(3 * H + j) * KM + k];
#pragma unroll
                for (int n = 0; n < NB; n++) {
                    float2 v = vin[k * BPC_ + n * GROUPS + group];
                    acc[0][n] = ffma2(w0, v, acc[0][n]);
                    acc[1][n] = ffma2(w1, v, acc[1][n]);
                    acc[2][n] = ffma2(w2, v, acc[2][n]);
                    acc[3][n] = ffma2(w3, v, acc[3][n]);
                }
            }
            // Activations in registers BEFORE the barrier (MUFU overlaps
            // other warps' FMA phase).
            float2 h2[NB];
#pragma unroll
            for (int n = 0; n < NB; n++) {
                h2[n].x = cell_one(acc[0][n].x, acc[1][n].x, acc[2][n].x,
                                   acc[3][n].x, c[p][n].x);
                h2[n].y = cell_one(acc[0][n].y, acc[1][n].y, acc[2][n].y,
                                   acc[3][n].y, c[p][n].y);
            }
            __syncthreads();   // all reads of h rows (t-1) done
            float2* hrow = rows + (p + 1) * H * BPC_ + j * BPC_;
#pragma unroll
            for (int n = 0; n < NB; n++) {
                int bp = n * GROUPS + group;
                hrow[bp] = h2[n];
                if (p == PACK - 1)
                    *reinterpret_cast<float2*>(&bout[j * BATCH + 2 * bp]) = h2[n];
            }
            __syncthreads();   // writes visible before next reads / release
        }
        if (!LAST && tid == 0) st_rel(fout + t, 1u);
    }
}

// ---------------------------------------------------------------------------
// Fused pipeline: 168 CTAs, 2 CTAs/SM co-residency => all resident.
// bids 0-127: stack3 (64 layers, batch-split NS=2)
// bids 128-159: stack2 (64 layers, 2 packed/block)
// bids 160-167: stack1 (32 layers, 4 packed/block)
// ---------------------------------------------------------------------------
__global__ void __launch_bounds__(BLOCK, 2)
lstm_pipe(const float* l1_Wih0, const float* l1_Whh0, const float* l1_bih0, const float* l1_bhh0,
          const float* l1_Wih,  const float* l1_Whh,  const float* l1_bih,  const float* l1_bhh,
          const float* l2_Wih0, const float* l2_Whh0, const float* l2_bih0, const float* l2_bhh0,
          const float* l2_Wih,  const float* l2_Whh,  const float* l2_bih,  const float* l2_bhh,
          const float* l3_Wih0, const float* l3_Whh0, const float* l3_bih0, const float* l3_bhh0,
          const float* l3_Wih,  const float* l3_Whh,  const float* l3_bih,  const float* l3_bhh)
{
    __shared__ __align__(16) float2 sW[2048];    // 16KB max (stack3)
    __shared__ __align__(16) float2 rows[3072];  // 24KB max (stack2)
    __shared__ float sB[256];

    const int bid = blockIdx.x;

    if (bid < 128) {                       // ---- stack3: H=16, NS=2
        const int d = bid >> 1, s = bid & 1;
        fill_layer<16, 8>(sW, sB, l3_Wih0, l3_Whh0, l3_bih0, l3_bhh0,
                          l3_Wih, l3_Whh, l3_bih, l3_bhh, d);
        const int q = 40 + d;
        const float* bufin = g_act[q & 1];
        float* bufout = g_act[(q + 1) & 1];
        const unsigned* fin = g_flags + (size_t)(d ? (40 + (d - 1) * 2 + s) : 39) * T_STEPS;
        unsigned* fout = g_flags + (size_t)(40 + d * 2 + s) * T_STEPS;
        const int b0 = s * 128;
        if (d == 0)
            stage_loop<16, 1, 64, 8, false, true, false>(sW, sB, rows, bufin, bufout, fin, fout, b0);
        else if (d == 63)
            stage_loop<16, 1, 64, 16, false, false, true>(sW, sB, rows, bufin, bufout, fin, fout, b0);
        else
            stage_loop<16, 1, 64, 16, false, false, false>(sW, sB, rows, bufin, bufout, fin, fout, b0);
    } else if (bid < 160) {                // ---- stack2: H=8, pack 2
        const int jd = bid - 128;
        fill_layer<8, 4>(sW, sB, l2_Wih0, l2_Whh0, l2_bih0, l2_bhh0,
                         l2_Wih, l2_Whh, l2_bih, l2_bhh, 2 * jd);
        fill_layer<8, 4>(sW + 4 * 8 * 16, sB + 32, l2_Wih0, l2_Whh0, l2_bih0, l2_bhh0,
                         l2_Wih, l2_Whh, l2_bih, l2_bhh, 2 * jd + 1);
        const int q = 8 + jd;
        const float* bufin = g_act[q & 1];
        float* bufout = g_act[(q + 1) & 1];
        const unsigned* fin = g_flags + (size_t)(jd ? (8 + jd - 1) : 7) * T_STEPS;
        unsigned* fout = g_flags + (size_t)(8 + jd) * T_STEPS;
        if (jd == 0)
            stage_loop<8, 2, 128, 4, false, true, false>(sW, sB, rows, bufin, bufout, fin, fout, 0);
        else
            stage_loop<8, 2, 128, 8, false, false, false>(sW, sB, rows, bufin, bufout, fin, fout, 0);
    } else {                               // ---- stack1: H=4, pack 4
        const int id = bid - 160;
#pragma unroll
        for (int p = 0; p < 4; p++)
            fill_layer<4, 2>(sW + p * 4 * 4 * 8, sB + p * 16,
                             l1_Wih0, l1_Whh0, l1_bih0, l1_bhh0,
                             l1_Wih, l1_Whh, l1_bih, l1_bhh, 4 * id + p);
        const int q = id;
        const float* bufin = g_act[q & 1];
        float* bufout = g_act[(q + 1) & 1];
        const unsigned* fin = g_flags + (size_t)(id ? id - 1 : 0) * T_STEPS;
        unsigned* fout = g_flags + (size_t)id * T_STEPS;
        if (id == 0)
            stage_loop<4, 4, 128, 2, true, false, false>(sW, sB, rows, bufin, bufout, fin, fout, 0);
        else
            stage_loop<4, 4, 128, 4, false, false, false>(sW, sB, rows, bufin, bufout, fin, fout, 0);
    }
}

// ---------------------------------------------------------------------------
// Pre: transpose x -> g_act[0][t][m][b] AND clear all flags (replay-safe).
// Post: ReLU + FC(16->4).
// ---------------------------------------------------------------------------
__global__ void pre_kernel(const float* __restrict__ x) {
    int t = blockIdx.x, b = threadIdx.x;
    float2 v = *reinterpret_cast<const float2*>(&x[((size_t)t * BATCH + b) * 2]);
    g_act[0][(t * 16 + 0) * BATCH + b] = v.x;
    g_act[0][(t * 16 + 1) * BATCH + b] = v.y;
    int idx = t * BLOCK + b;
    if (idx < NFLAGS * T_STEPS) g_flags[idx] = 0;
}

__global__ void fc_kernel(const float* __restrict__ fcW, const float* __restrict__ fcb,
                          float* __restrict__ out) {
    int t = blockIdx.x, b = threadIdx.x;
    float v[16];
#pragma unroll
    for (int m = 0; m < 16; m++)
        v[m] = fmaxf(g_act[0][(t * 16 + m) * BATCH + b], 0.f);
#pragma unroll
    for (int q = 0; q < 4; q++) {
        float a = fcb[q];
#pragma unroll
        for (int m = 0; m < 16; m++) a = fmaf(v[m], fcW[q * 16 + m], a);
        out[((size_t)t * BATCH + b) * 4 + q] = a;
    }
}

// ---------------------------------------------------------------------------
extern "C" void kernel_launch(void* const* d_in, const int* in_sizes, int n_in,
                              void* d_out, int out_size) {
#define F(i) ((const float*)d_in[i])
    pre_kernel<<<T_STEPS, BATCH>>>(F(0));
    lstm_pipe<<<GRID, BLOCK>>>(
        F(1), F(2), F(3), F(4), F(5), F(6), F(7), F(8),
        F(9), F(10), F(11), F(12), F(13), F(14), F(15), F(16),
        F(17), F(18), F(19), F(20), F(21), F(22), F(23), F(24));
    fc_kernel<<<T_STEPS, BATCH>>>(F(25), F(26), (float*)d_out);
#undef F
}

// round 5
// speedup vs baseline: 1.6326x; 1.2537x over previous
#include <cuda_runtime.h>

#define T_STEPS 512
#define BATCH   256
#define NSTAGES 144      // 16 s1 + 64 s2 + 64 s3 stage indices
#define WG      128      // threads per warpgroup

// Ping-pong activation buffers, layout [t][feature(16)][batch]
__device__ __align__(16) float g_act[2][T_STEPS * 16 * BATCH];
// Flags [stage][split(2)][t]; cleared by pre_kernel each replay.
__device__ unsigned g_flags[NSTAGES * 2 * T_STEPS];

// ---------------------------------------------------------------------------
__device__ __forceinline__ unsigned ld_acq(const unsigned* p) {
    unsigned v;
    asm volatile("ld.acquire.gpu.global.u32 %0, [%1];" : "=r"(v) : "l"(p) : "memory");
    return v;
}
__device__ __forceinline__ void st_rel(unsigned* p, unsigned v) {
    asm volatile("st.release.gpu.global.u32 [%0], %1;" :: "l"(p), "r"(v) : "memory");
}
__device__ __forceinline__ float2 ffma2(float2 a, float2 b, float2 c) {
    float2 d;
    asm("fma.rn.f32x2 %0, %1, %2, %3;"
        : "=l"(reinterpret_cast<unsigned long long&>(d))
        : "l"(reinterpret_cast<unsigned long long&>(a)),
          "l"(reinterpret_cast<unsigned long long&>(b)),
          "l"(reinterpret_cast<unsigned long long&>(c)));
    return d;
}
template<int ID>
__device__ __forceinline__ void wg_bar() {
    asm volatile("bar.sync %0, %1;" :: "r"(ID), "r"(WG) : "memory");
}

// Exact LSTM nonlinearity, shared-denominator form: 5 ex2 + 2 rcp.
__device__ __forceinline__ float cell_one(float gi, float gf, float gg, float go,
                                          float& c) {
    gi = fminf(fmaxf(gi, -15.f), 15.f);
    gf = fminf(fmaxf(gf, -15.f), 15.f);
    gg = fminf(fmaxf(gg, -15.f), 15.f);
    go = fminf(fmaxf(go, -15.f), 15.f);
    float a  = __expf(-gi);
    float fe = __expf(-gf);
    float b  = __expf(-2.f * gg);
    float na = 1.f + a, nf = 1.f + fe, nb = 1.f + b;
    float num = fmaf(c * na, nb, (1.f - b) * nf);
    c = __fdividef(num, nf * na * nb);
    float ct = fminf(fmaxf(c, -15.f), 15.f);
    float d  = __expf(-2.f * ct);
    float oe = __expf(-go);
    return __fdividef(1.f - d, (1.f + oe) * (1.f + d));
}

// ---------------------------------------------------------------------------
// Scalar weight fill: W[g][k], k<din from Wih, [din,H) zero, [H,2H) from Whh.
// ---------------------------------------------------------------------------
template<int H, int DIN0>
__device__ void fill_s(float* W, float* B,
                       const float* Wih0, const float* Whh0,
                       const float* bih0, const float* bhh0,
                       const float* Wih,  const float* Whh,
                       const float* bih,  const float* bhh, int l, int wtid) {
    constexpr int G = 4 * H, KM = 2 * H;
    const float* wi = l ? Wih + (size_t)(l - 1) * G * H : Wih0;
    const float* wh = l ? Whh + (size_t)(l - 1) * G * H : Whh0;
    const float* bi = l ? bih + (l - 1) * G : bih0;
    const float* bh = l ? bhh + (l - 1) * G : bhh0;
    const int din = l ? H : DIN0;
    for (int i = wtid; i < G * KM; i += WG) {
        int g = i / KM, k = i % KM;
        float w = 0.f;
        if (k < din)     w = wi[g * din + k];
        else if (k >= H) w = wh[g * H + (k - H)];
        W[i] = w;
    }
    for (int i = wtid; i < G; i += WG) B[i] = bi[i] + bh[i];
}

// ---------------------------------------------------------------------------
// Warpgroup stage loop (PACK layers fused). 128 threads.
// rows: [0,H) staged input (upper rows zero), layer p h at [(p+1)H,(p+2)H).
// ---------------------------------------------------------------------------
template<int H, int PACK, int BPC_, int DSTAGE, bool FIRST, bool RELU, bool LAST, int BARID>
__device__ void stage_loop(const float* __restrict__ sW, const float* __restrict__ sB,
                           float2* rows,
                           const float* __restrict__ bufin, float* __restrict__ bufout,
                           const unsigned* fin, unsigned* fout, int b0, int wtid) {
    constexpr int GROUPS = WG / H;
    constexpr int NB = BPC_ / GROUPS;
    constexpr int KM = 2 * H;
    const int j = wtid / GROUPS, group = wtid % GROUPS;

    float2 c[PACK][NB];
#pragma unroll
    for (int p = 0; p < PACK; p++)
#pragma unroll
        for (int n = 0; n < NB; n++) c[p][n] = make_float2(0.f, 0.f);

    for (int i = wtid; i < (PACK + 1) * H * BPC_; i += WG)
        rows[i] = make_float2(0.f, 0.f);
    wg_bar<BARID>();   // also orders weight fill before use

    for (int t = 0; t < T_STEPS; t++) {
        if (!FIRST) {
            const unsigned* f = fin + t;
            while (ld_acq(f) == 0) { }
        }
        const float* bin = bufin + (size_t)t * 16 * BATCH + b0;
#pragma unroll
        for (int i = wtid; i < DSTAGE * (BPC_ / 2); i += WG) {
            int m = i / (BPC_ / 2), q4 = i % (BPC_ / 2);
            float4 v = __ldcg(reinterpret_cast<const float4*>(&bin[m * BATCH + 4 * q4]));
            if (RELU) {
                v.x = fmaxf(v.x, 0.f); v.y = fmaxf(v.y, 0.f);
                v.z = fmaxf(v.z, 0.f); v.w = fmaxf(v.w, 0.f);
            }
            *reinterpret_cast<float4*>(&rows[m * BPC_ + 2 * q4]) = v;
        }
        wg_bar<BARID>();

        float* bout = bufout + (size_t)t * 16 * BATCH + b0;
#pragma unroll
        for (int p = 0; p < PACK; p++) {
            const float* W = sW + p * 4 * H * KM;
            const float* B = sB + p * 4 * H;
            const float2* vin = rows + p * H * BPC_;

            float2 acc[4][NB];
#pragma unroll
            for (int q = 0; q < 4; q++) {
                float bv = B[q * H + j];
#pragma unroll
                for (int n = 0; n < NB; n++) acc[q][n] = make_float2(bv, bv);
            }
#pragma unroll 4
            for (int k = 0; k < KM; k++) {
                float s0 = W[(0 * H + j) * KM + k];
                float s1 = W[(1 * H + j) * KM + k];
                float s2 = W[(2 * H + j) * KM + k];
                float s3 = W[(3 * H + j) * KM + k];
                float2 w0 = make_float2(s0, s0), w1 = make_float2(s1, s1);
                float2 w2 = make_float2(s2, s2), w3 = make_float2(s3, s3);
#pragma unroll
                for (int n = 0; n < NB; n++) {
                    float2 v = vin[k * BPC_ + n * GROUPS + group];
                    acc[0][n] = ffma2(w0, v, acc[0][n]);
                    acc[1][n] = ffma2(w1, v, acc[1][n]);
                    acc[2][n] = ffma2(w2, v, acc[2][n]);
                    acc[3][n] = ffma2(w3, v, acc[3][n]);
                }
            }
            float2 h2[NB];
#pragma unroll
            for (int n = 0; n < NB; n++) {
                h2[n].x = cell_one(acc[0][n].x, acc[1][n].x, acc[2][n].x,
                                   acc[3][n].x, c[p][n].x);
                h2[n].y = cell_one(acc[0][n].y, acc[1][n].y, acc[2][n].y,
                                   acc[3][n].y, c[p][n].y);
            }
            wg_bar<BARID>();   // all reads of h(t-1)/input done before overwrite
            float2* hrow = rows + (p + 1) * H * BPC_ + j * BPC_;
#pragma unroll
            for (int n = 0; n < NB; n++) {
                int bp = n * GROUPS + group;
                hrow[bp] = h2[n];
                if (p == PACK - 1)
                    *reinterpret_cast<float2*>(&bout[j * BATCH + 2 * bp]) = h2[n];
            }
            wg_bar<BARID>();
        }
        if (!LAST && wtid == 0) st_rel(fout + t, 1u);
    }
}

// ---------------------------------------------------------------------------
// 128 CTAs (one per SM), 2 warpgroups each:
//  WG0 (tid<128): stack3 half-batch unit (layer cta>>1, split cta&1)
//  WG1: cta<64 -> stack2 layer cta; cta in [64,80) -> stack1 pack2; else idle
// Stage indices q: s1 units 0..15, s2 16..79, s3 80..143.
// ---------------------------------------------------------------------------
__global__ void __launch_bounds__(256, 1)
lstm_pipe(const float* l1_Wih0, const float* l1_Whh0, const float* l1_bih0, const float* l1_bhh0,
          const float* l1_Wih,  const float* l1_Whh,  const float* l1_bih,  const float* l1_bhh,
          const float* l2_Wih0, const float* l2_Whh0, const float* l2_bih0, const float* l2_bhh0,
          const float* l2_Wih,  const float* l2_Whh,  const float* l2_bih,  const float* l2_bhh,
          const float* l3_Wih0, const float* l3_Whh0, const float* l3_bih0, const float* l3_bhh0,
          const float* l3_Wih,  const float* l3_Whh,  const float* l3_bih,  const float* l3_bhh)
{
    __shared__ float sW0[64 * 32];                     // 8KB  s3 weights
    __shared__ float sB0[64];
    __shared__ __align__(16) float2 rows0[2 * 16 * 64];  // 16KB s3 rows
    __shared__ float sW1[512];                         // 2KB  s2 / s1-pack2
    __shared__ float sB1[64];
    __shared__ __align__(16) float2 rows1[2048];       // 16KB

    const int tid = threadIdx.x, cta = blockIdx.x;

    if (tid < WG) {
        // ---- WG0: stack3 half-batch ----
        const int wtid = tid;
        const int d = cta >> 1, s = cta & 1;
        fill_s<16, 8>(sW0, sB0, l3_Wih0, l3_Whh0, l3_bih0, l3_bhh0,
                      l3_Wih, l3_Whh, l3_bih, l3_bhh, d, wtid);
        const int q = 80 + d;
        const float* bufin = g_act[q & 1];
        float* bufout = g_act[(q + 1) & 1];
        const unsigned* fin = (d == 0)
            ? g_flags + (size_t)(79 * 2 + 0) * T_STEPS
            : g_flags + (size_t)((q - 1) * 2 + s) * T_STEPS;
        unsigned* fout = g_flags + (size_t)(q * 2 + s) * T_STEPS;
        const int b0 = s * 128;
        if (d == 0)
            stage_loop<16, 1, 64, 8, false, true, false, 1>(sW0, sB0, rows0, bufin, bufout, fin, fout, b0, wtid);
        else if (d == 63)
            stage_loop<16, 1, 64, 16, false, false, true, 1>(sW0, sB0, rows0, bufin, bufout, fin, fout, b0, wtid);
        else
            stage_loop<16, 1, 64, 16, false, false, false, 1>(sW0, sB0, rows0, bufin, bufout, fin, fout, b0, wtid);
    } else if (cta < 64) {
        // ---- WG1: stack2 single layer ----
        const int wtid = tid - WG;
        const int u = cta, q = 16 + u;
        fill_s<8, 4>(sW1, sB1, l2_Wih0, l2_Whh0, l2_bih0, l2_bhh0,
                     l2_Wih, l2_Whh, l2_bih, l2_bhh, u, wtid);
        const float* bufin = g_act[q & 1];
        float* bufout = g_act[(q + 1) & 1];
        const unsigned* fin = g_flags + (size_t)((q - 1) * 2) * T_STEPS;
        unsigned* fout = g_flags + (size_t)(q * 2) * T_STEPS;
        if (u == 0)
            stage_loop<8, 1, 128, 4, false, true, false, 2>(sW1, sB1, rows1, bufin, bufout, fin, fout, 0, wtid);
        else
            stage_loop<8, 1, 128, 8, false, false, false, 2>(sW1, sB1, rows1, bufin, bufout, fin, fout, 0, wtid);
    } else if (cta < 80) {
        // ---- WG1: stack1 pack2 ----
        const int wtid = tid - WG;
        const int i = cta - 64, q = i;
        fill_s<4, 2>(sW1, sB1, l1_Wih0, l1_Whh0, l1_bih0, l1_bhh0,
                     l1_Wih, l1_Whh, l1_bih, l1_bhh, 2 * i, wtid);
        fill_s<4, 2>(sW1 + 16 * 8, sB1 + 16, l1_Wih0, l1_Whh0, l1_bih0, l1_bhh0,
                     l1_Wih, l1_Whh, l1_bih, l1_bhh, 2 * i + 1, wtid);
        const float* bufin = g_act[q & 1];
        float* bufout = g_act[(q + 1) & 1];
        const unsigned* fin = g_flags + (size_t)((q > 0 ? q - 1 : 0) * 2) * T_STEPS;
        unsigned* fout = g_flags + (size_t)(q * 2) * T_STEPS;
        if (i == 0)
            stage_loop<4, 2, 128, 2, true, false, false, 2>(sW1, sB1, rows1, bufin, bufout, fin, fout, 0, wtid);
        else
            stage_loop<4, 2, 128, 4, false, false, false, 2>(sW1, sB1, rows1, bufin, bufout, fin, fout, 0, wtid);
    }
    // else: idle WG1 threads exit
}

// ---------------------------------------------------------------------------
// Pre: transpose x -> g_act[0][t][m][b] AND clear all flags (replay-safe).
// Post: ReLU + FC(16->4).
// ---------------------------------------------------------------------------
__global__ void pre_kernel(const float* __restrict__ x) {
    int t = blockIdx.x, b = threadIdx.x;
    float2 v = *reinterpret_cast<const float2*>(&x[((size_t)t * BATCH + b) * 2]);
    g_act[0][(t * 16 + 0) * BATCH + b] = v.x;
    g_act[0][(t * 16 + 1) * BATCH + b] = v.y;
    int idx = t * BATCH + b;
    for (int i = idx; i < NSTAGES * 2 * T_STEPS; i += T_STEPS * BATCH)
        g_flags[i] = 0;
}

__global__ void fc_kernel(const float* __restrict__ fcW, const float* __restrict__ fcb,
                          float* __restrict__ out) {
    int t = blockIdx.x, b = threadIdx.x;
    float v[16];
#pragma unroll
    for (int m = 0; m < 16; m++)
        v[m] = fmaxf(g_act[0][(t * 16 + m) * BATCH + b], 0.f);
#pragma unroll
    for (int q = 0; q < 4; q++) {
        float a = fcb[q];
#pragma unroll
        for (int m = 0; m < 16; m++) a = fmaf(v[m], fcW[q * 16 + m], a);
        out[((size_t)t * BATCH + b) * 4 + q] = a;
    }
}

// ---------------------------------------------------------------------------
extern "C" void kernel_launch(void* const* d_in, const int* in_sizes, int n_in,
                              void* d_out, int out_size) {
#define F(i) ((const float*)d_in[i])
    pre_kernel<<<T_STEPS, BATCH>>>(F(0));
    lstm_pipe<<<128, 256>>>(
        F(1), F(2), F(3), F(4), F(5), F(6), F(7), F(8),
        F(9), F(10), F(11), F(12), F(13), F(14), F(15), F(16),
        F(17), F(18), F(19), F(20), F(21), F(22), F(23), F(24));
    fc_kernel<<<T_STEPS, BATCH>>>(F(25), F(26), (float*)d_out);
#undef F
}